// round 1
// baseline (speedup 1.0000x reference)
#include <cuda_runtime.h>
#include <cstdint>

#define BATCH 8
#define NTOK  4096
#define CIN   192
#define HID   768
#define EPSBN 1e-5f

// Scratch: hidden activations, stored TRANSPOSED as [B, H, N] so the FFT along
// tokens is contiguous and GEMM2 reads K-major rows. ~100.7 MB.
__device__ float  g_ht[(size_t)BATCH * HID * NTOK];
__device__ float2 g_tw[NTOK];   // forward twiddles e^{-2*pi*i*t/N}

// ---------------------------------------------------------------------------
// Twiddle table init (re-run every launch; deterministic)
// ---------------------------------------------------------------------------
__global__ void twiddle_init_k()
{
    int t = blockIdx.x * blockDim.x + threadIdx.x;
    if (t < NTOK) {
        float s, c;
        sincospif(-2.0f * (float)t / (float)NTOK, &s, &c);
        g_tw[t] = make_float2(c, s);
    }
}

// ---------------------------------------------------------------------------
// Shared-tile loader: 64 rows x 32 cols from row-major src (leading dim ld),
// stored TRANSPOSED into s[k][row] with row stride 68 (pad keeps float4 align
// for compute loads and reduces store conflicts).
// ---------------------------------------------------------------------------
__device__ __forceinline__ void load_tile_T(const float* __restrict__ src, int ld,
                                            float* __restrict__ s)
{
    int t   = threadIdx.x;
    int row = t >> 3;          // 0..31
    int col = (t & 7) << 2;    // 0,4,...,28
#pragma unroll
    for (int rr = 0; rr < 2; rr++) {
        int r0 = row + rr * 32;
        float4 v = *(const float4*)(src + (size_t)r0 * ld + col);
        s[(col + 0) * 68 + r0] = v.x;
        s[(col + 1) * 68 + r0] = v.y;
        s[(col + 2) * 68 + r0] = v.z;
        s[(col + 3) * 68 + r0] = v.w;
    }
}

// ---------------------------------------------------------------------------
// GEMM1: ht[b,h,n] = relu(BN( sum_c x[b,n,c] * W1[h,c] ))
// 64x64 tile, K=192 in chunks of 32, 4x4 microtile, 256 threads.
// ---------------------------------------------------------------------------
__global__ __launch_bounds__(256) void gemm1_k(
    const float* __restrict__ x,  const float* __restrict__ W1,
    const float* __restrict__ g1, const float* __restrict__ b1,
    const float* __restrict__ m1, const float* __restrict__ v1)
{
    __shared__ float sA[32 * 68];   // sA[k][h]
    __shared__ float sB[32 * 68];   // sB[k][n]

    int n0 = blockIdx.x * 64;
    int h0 = blockIdx.y * 64;
    int b  = blockIdx.z;
    int tid = threadIdx.x;
    int tx = tid & 15;      // n microtile index
    int ty = tid >> 4;      // h microtile index

    const float* Aorig = W1 + (size_t)h0 * CIN;
    const float* Borig = x + ((size_t)b * NTOK + n0) * CIN;

    float acc[4][4];
#pragma unroll
    for (int i = 0; i < 4; i++)
#pragma unroll
        for (int j = 0; j < 4; j++) acc[i][j] = 0.0f;

    for (int kc = 0; kc < CIN; kc += 32) {
        load_tile_T(Aorig + kc, CIN, sA);
        load_tile_T(Borig + kc, CIN, sB);
        __syncthreads();
#pragma unroll
        for (int k = 0; k < 32; k++) {
            const float4 a  = *(const float4*)(sA + k * 68 + (ty << 2));
            const float4 bv = *(const float4*)(sB + k * 68 + (tx << 2));
            acc[0][0] = fmaf(a.x, bv.x, acc[0][0]);
            acc[0][1] = fmaf(a.x, bv.y, acc[0][1]);
            acc[0][2] = fmaf(a.x, bv.z, acc[0][2]);
            acc[0][3] = fmaf(a.x, bv.w, acc[0][3]);
            acc[1][0] = fmaf(a.y, bv.x, acc[1][0]);
            acc[1][1] = fmaf(a.y, bv.y, acc[1][1]);
            acc[1][2] = fmaf(a.y, bv.z, acc[1][2]);
            acc[1][3] = fmaf(a.y, bv.w, acc[1][3]);
            acc[2][0] = fmaf(a.z, bv.x, acc[2][0]);
            acc[2][1] = fmaf(a.z, bv.y, acc[2][1]);
            acc[2][2] = fmaf(a.z, bv.z, acc[2][2]);
            acc[2][3] = fmaf(a.z, bv.w, acc[2][3]);
            acc[3][0] = fmaf(a.w, bv.x, acc[3][0]);
            acc[3][1] = fmaf(a.w, bv.y, acc[3][1]);
            acc[3][2] = fmaf(a.w, bv.z, acc[3][2]);
            acc[3][3] = fmaf(a.w, bv.w, acc[3][3]);
        }
        __syncthreads();
    }

#pragma unroll
    for (int i = 0; i < 4; i++) {
        int h = h0 + (ty << 2) + i;
        float sc = g1[h] * rsqrtf(v1[h] + EPSBN);
        float sh = b1[h] - m1[h] * sc;
        float4 o;
        o.x = fmaxf(fmaf(acc[i][0], sc, sh), 0.0f);
        o.y = fmaxf(fmaf(acc[i][1], sc, sh), 0.0f);
        o.z = fmaxf(fmaf(acc[i][2], sc, sh), 0.0f);
        o.w = fmaxf(fmaf(acc[i][3], sc, sh), 0.0f);
        *(float4*)(g_ht + ((size_t)(b * HID + h) * NTOK + n0 + (tx << 2))) = o;
    }
}

// ---------------------------------------------------------------------------
// Fused FFT -> pointwise -> IFFT, one CTA per (b,h) row of g_ht (in place).
// Radix-4 Stockham autosort, 6 stages, ping-pong in dynamic shared (64 KB).
// ---------------------------------------------------------------------------
__device__ __forceinline__ float2 cmulf(float2 a, float2 b)
{
    return make_float2(fmaf(a.x, b.x, -a.y * b.y), fmaf(a.x, b.y, a.y * b.x));
}

template <bool INV, int NS>
__device__ __forceinline__ void fft_stage(const float2* __restrict__ src,
                                          float2* __restrict__ dst)
{
    constexpr int STEP = (NTOK / 4) / NS;   // 1024/NS
#pragma unroll
    for (int q = 0; q < 4; q++) {
        int j = threadIdx.x + q * 256;      // 0..1023
        int k = j & (NS - 1);
        float2 a0 = src[j];
        float2 a1 = src[j + 1024];
        float2 a2 = src[j + 2048];
        float2 a3 = src[j + 3072];
        int kk = k * STEP;
        float2 w1 = g_tw[kk];
        float2 w2 = g_tw[2 * kk];
        float2 w3 = g_tw[3 * kk];
        if (INV) { w1.y = -w1.y; w2.y = -w2.y; w3.y = -w3.y; }
        a1 = cmulf(w1, a1);
        a2 = cmulf(w2, a2);
        a3 = cmulf(w3, a3);
        float2 t0 = make_float2(a0.x + a2.x, a0.y + a2.y);
        float2 t1 = make_float2(a0.x - a2.x, a0.y - a2.y);
        float2 t2 = make_float2(a1.x + a3.x, a1.y + a3.y);
        float2 u  = make_float2(a1.x - a3.x, a1.y - a3.y);
        float2 t3 = INV ? make_float2(-u.y, u.x) : make_float2(u.y, -u.x);
        int base = ((j - k) << 2) + k;      // (j/NS)*4*NS + k
        dst[base         ] = make_float2(t0.x + t2.x, t0.y + t2.y);
        dst[base +     NS] = make_float2(t1.x + t3.x, t1.y + t3.y);
        dst[base + 2 * NS] = make_float2(t0.x - t2.x, t0.y - t2.y);
        dst[base + 3 * NS] = make_float2(t1.x - t3.x, t1.y - t3.y);
    }
    __syncthreads();
}

template <bool INV>
__device__ __forceinline__ void fft6(float2* b0, float2* b1)
{
    fft_stage<INV, 1>(b0, b1);
    fft_stage<INV, 4>(b1, b0);
    fft_stage<INV, 16>(b0, b1);
    fft_stage<INV, 64>(b1, b0);
    fft_stage<INV, 256>(b0, b1);
    fft_stage<INV, 1024>(b1, b0);   // result lands back in b0
}

__global__ __launch_bounds__(256) void fftmix_k(
    const float* __restrict__ rmat, const float* __restrict__ imat,
    const float* __restrict__ rb,   const float* __restrict__ ib)
{
    extern __shared__ float2 sb[];
    float2* b0 = sb;
    float2* b1 = sb + NTOK;

    int blk = blockIdx.x;              // b*HID + h
    int h   = blk % HID;
    float* row = g_ht + (size_t)blk * NTOK;
    int tid = threadIdx.x;

#pragma unroll
    for (int q = 0; q < 16; q++) {
        int t = tid + q * 256;
        b0[t] = make_float2(row[t], 0.0f);
    }
    __syncthreads();

    fft6<false>(b0, b1);

    float ra  = rmat[(size_t)h * HID + h];   // diag(r)
    float ia  = imat[(size_t)h * HID + h];   // diag(i)
    float rbv = rb[h];
    float ibv = ib[h];
    const float inv = 0.015625f;             // 1/sqrt(4096)

#pragma unroll
    for (int q = 0; q < 16; q++) {
        int t = tid + q * 256;
        float2 v = b0[t];
        float re = v.x * inv;
        float im = v.y * inv;
        float xr = fmaxf(fmaf(ra, re, fmaf(-ia, im, rbv)), 0.0f);
        float xi = fmaxf(fmaf(ra, im, fmaf(ia, re, ibv)), 0.0f);
        b0[t] = make_float2(xr, xi);
    }
    __syncthreads();

    fft6<true>(b0, b1);

#pragma unroll
    for (int q = 0; q < 16; q++) {
        int t = tid + q * 256;
        row[t] = b0[t].x * inv;
    }
}

// ---------------------------------------------------------------------------
// GEMM2: y[b,n,c] = BN( sum_h ht[b,h,n] * W2[c,h] )
// A = W2 [192,768] (transposed on store), B = ht rows (direct copy).
// Microtile mapping: tx -> c, ty -> n (so the epilogue stores contiguous c).
// ---------------------------------------------------------------------------
__global__ __launch_bounds__(256) void gemm2_k(
    const float* __restrict__ W2,
    const float* __restrict__ g2, const float* __restrict__ b2,
    const float* __restrict__ m2, const float* __restrict__ v2,
    float* __restrict__ y)
{
    __shared__ float sA[32 * 68];   // sA[k][c]
    __shared__ float sB[32 * 68];   // sB[k][n]

    int n0 = blockIdx.x * 64;
    int c0 = blockIdx.y * 64;
    int b  = blockIdx.z;
    int tid = threadIdx.x;
    int tx = tid & 15;      // c microtile
    int ty = tid >> 4;      // n microtile

    const float* Aorig = W2 + (size_t)c0 * HID;
    const float* Borig = g_ht + (size_t)b * HID * NTOK + n0;

    float acc[4][4];        // acc[n][c]
#pragma unroll
    for (int i = 0; i < 4; i++)
#pragma unroll
        for (int j = 0; j < 4; j++) acc[i][j] = 0.0f;

    for (int kc = 0; kc < HID; kc += 32) {
        load_tile_T(Aorig + kc, HID, sA);
        {   // direct copy 32 (h-rows) x 64 (n) tile of ht
            int rowk = tid >> 4;          // 0..15
            int col  = (tid & 15) << 2;   // 0..60
#pragma unroll
            for (int rr = 0; rr < 2; rr++) {
                int k = rowk + rr * 16;
                float4 v = *(const float4*)(Borig + (size_t)(kc + k) * NTOK + col);
                *(float4*)(sB + k * 68 + col) = v;
            }
        }
        __syncthreads();
#pragma unroll
        for (int k = 0; k < 32; k++) {
            const float4 a  = *(const float4*)(sA + k * 68 + (tx << 2));  // c
            const float4 bn = *(const float4*)(sB + k * 68 + (ty << 2));  // n
            acc[0][0] = fmaf(bn.x, a.x, acc[0][0]);
            acc[0][1] = fmaf(bn.x, a.y, acc[0][1]);
            acc[0][2] = fmaf(bn.x, a.z, acc[0][2]);
            acc[0][3] = fmaf(bn.x, a.w, acc[0][3]);
            acc[1][0] = fmaf(bn.y, a.x, acc[1][0]);
            acc[1][1] = fmaf(bn.y, a.y, acc[1][1]);
            acc[1][2] = fmaf(bn.y, a.z, acc[1][2]);
            acc[1][3] = fmaf(bn.y, a.w, acc[1][3]);
            acc[2][0] = fmaf(bn.z, a.x, acc[2][0]);
            acc[2][1] = fmaf(bn.z, a.y, acc[2][1]);
            acc[2][2] = fmaf(bn.z, a.z, acc[2][2]);
            acc[2][3] = fmaf(bn.z, a.w, acc[2][3]);
            acc[3][0] = fmaf(bn.w, a.x, acc[3][0]);
            acc[3][1] = fmaf(bn.w, a.y, acc[3][1]);
            acc[3][2] = fmaf(bn.w, a.z, acc[3][2]);
            acc[3][3] = fmaf(bn.w, a.w, acc[3][3]);
        }
        __syncthreads();
    }

    float sc[4], sh[4];
#pragma unroll
    for (int j = 0; j < 4; j++) {
        int c = c0 + (tx << 2) + j;
        sc[j] = g2[c] * rsqrtf(v2[c] + EPSBN);
        sh[j] = b2[c] - m2[c] * sc[j];
    }
#pragma unroll
    for (int i = 0; i < 4; i++) {
        int n = n0 + (ty << 2) + i;
        float4 o;
        o.x = fmaf(acc[i][0], sc[0], sh[0]);
        o.y = fmaf(acc[i][1], sc[1], sh[1]);
        o.z = fmaf(acc[i][2], sc[2], sh[2]);
        o.w = fmaf(acc[i][3], sc[3], sh[3]);
        *(float4*)(y + ((size_t)(b * NTOK + n) * CIN + c0 + (tx << 2))) = o;
    }
}

// ---------------------------------------------------------------------------
extern "C" void kernel_launch(void* const* d_in, const int* in_sizes, int n_in,
                              void* d_out, int out_size)
{
    const float* x  = (const float*)d_in[0];
    const float* W1 = (const float*)d_in[1];
    const float* g1 = (const float*)d_in[2];
    const float* b1 = (const float*)d_in[3];
    const float* m1 = (const float*)d_in[4];
    const float* v1 = (const float*)d_in[5];
    const float* r  = (const float*)d_in[6];
    const float* im = (const float*)d_in[7];
    const float* rb = (const float*)d_in[8];
    const float* ib = (const float*)d_in[9];
    const float* W2 = (const float*)d_in[10];
    const float* g2 = (const float*)d_in[11];
    const float* b2 = (const float*)d_in[12];
    const float* m2 = (const float*)d_in[13];
    const float* v2 = (const float*)d_in[14];
    float* y = (float*)d_out;

    cudaFuncSetAttribute(fftmix_k, cudaFuncAttributeMaxDynamicSharedMemorySize, 65536);

    twiddle_init_k<<<16, 256>>>();
    gemm1_k<<<dim3(NTOK / 64, HID / 64, BATCH), 256>>>(x, W1, g1, b1, m1, v1);
    fftmix_k<<<BATCH * HID, 256, 65536>>>(r, im, rb, ib);
    gemm2_k<<<dim3(NTOK / 64, CIN / 64, BATCH), 256>>>(W2, g2, b2, m2, v2, y);
}

// round 2
// speedup vs baseline: 1.3068x; 1.3068x over previous
#include <cuda_runtime.h>
#include <cstdint>

#define BATCH 8
#define NTOK  4096
#define CIN   192
#define HID   768
#define EPSBN 1e-5f

// Scratch: hidden activations, TRANSPOSED [B, H, N] so FFT rows are contiguous
// and GEMM2 reads K-major rows. ~100.7 MB.
__device__ float  g_ht[(size_t)BATCH * HID * NTOK];
__device__ float2 g_tw[NTOK];   // forward twiddles e^{-2*pi*i*t/N}

// padded smem index for FFT buffers: one extra float2 per 32
#define PAD(i) ((i) + ((i) >> 5))
#define FFT_BUF 4224            // PAD(4095)=4222 < 4224

// ---------------------------------------------------------------------------
__global__ void twiddle_init_k()
{
    int t = blockIdx.x * blockDim.x + threadIdx.x;
    if (t < NTOK) {
        float s, c;
        sincospif(-2.0f * (float)t / (float)NTOK, &s, &c);
        g_tw[t] = make_float2(c, s);
    }
}

// ---------------------------------------------------------------------------
// GEMM1: ht[b,h,n] = relu(BN( sum_c x[b,n,c] * W1[h,c] ))
// 128(n) x 128(h) x 16(k) tile, 8x8 microtile, 256 threads.
// ---------------------------------------------------------------------------
__global__ __launch_bounds__(256) void gemm1_k(
    const float* __restrict__ x,  const float* __restrict__ W1,
    const float* __restrict__ g1, const float* __restrict__ b1,
    const float* __restrict__ m1, const float* __restrict__ v1)
{
    __shared__ float sX[16][132];   // [k][n]
    __shared__ float sW[16][132];   // [k][h]

    int tid = threadIdx.x;
    int n0 = blockIdx.x * 128;
    int h0 = blockIdx.y * 128;
    int b  = blockIdx.z;

    int lrow = tid >> 2;            // 0..63
    int lk4  = (tid & 3) << 2;      // 0,4,8,12

    const float* xp = x  + ((size_t)b * NTOK + n0) * CIN;
    const float* wp = W1 + (size_t)h0 * CIN;

    int tx = tid & 15;              // n group
    int ty = tid >> 4;              // h group

    float acc[8][8];
#pragma unroll
    for (int i = 0; i < 8; i++)
#pragma unroll
        for (int j = 0; j < 8; j++) acc[i][j] = 0.0f;

    for (int kc = 0; kc < CIN; kc += 16) {
#pragma unroll
        for (int rr = 0; rr < 2; rr++) {
            int row = lrow + rr * 64;
            float4 vx = *(const float4*)(xp + (size_t)row * CIN + kc + lk4);
            float4 vw = *(const float4*)(wp + (size_t)row * CIN + kc + lk4);
            sX[lk4 + 0][row] = vx.x; sX[lk4 + 1][row] = vx.y;
            sX[lk4 + 2][row] = vx.z; sX[lk4 + 3][row] = vx.w;
            sW[lk4 + 0][row] = vw.x; sW[lk4 + 1][row] = vw.y;
            sW[lk4 + 2][row] = vw.z; sW[lk4 + 3][row] = vw.w;
        }
        __syncthreads();
#pragma unroll
        for (int k = 0; k < 16; k++) {
            float a[8], bb[8];
            *(float4*)(a)      = *(const float4*)(&sW[k][ty * 8]);
            *(float4*)(a + 4)  = *(const float4*)(&sW[k][ty * 8 + 4]);
            *(float4*)(bb)     = *(const float4*)(&sX[k][tx * 8]);
            *(float4*)(bb + 4) = *(const float4*)(&sX[k][tx * 8 + 4]);
#pragma unroll
            for (int i = 0; i < 8; i++)
#pragma unroll
                for (int j = 0; j < 8; j++)
                    acc[i][j] = fmaf(a[i], bb[j], acc[i][j]);
        }
        __syncthreads();
    }

#pragma unroll
    for (int i = 0; i < 8; i++) {
        int h = h0 + ty * 8 + i;
        float sc = g1[h] * rsqrtf(v1[h] + EPSBN);
        float sh = b1[h] - m1[h] * sc;
        float* op = g_ht + ((size_t)(b * HID + h) * NTOK + n0 + tx * 8);
        float4 o0, o1;
        o0.x = fmaxf(fmaf(acc[i][0], sc, sh), 0.0f);
        o0.y = fmaxf(fmaf(acc[i][1], sc, sh), 0.0f);
        o0.z = fmaxf(fmaf(acc[i][2], sc, sh), 0.0f);
        o0.w = fmaxf(fmaf(acc[i][3], sc, sh), 0.0f);
        o1.x = fmaxf(fmaf(acc[i][4], sc, sh), 0.0f);
        o1.y = fmaxf(fmaf(acc[i][5], sc, sh), 0.0f);
        o1.z = fmaxf(fmaf(acc[i][6], sc, sh), 0.0f);
        o1.w = fmaxf(fmaf(acc[i][7], sc, sh), 0.0f);
        *(float4*)(op)     = o0;
        *(float4*)(op + 4) = o1;
    }
}

// ---------------------------------------------------------------------------
// Fused FFT -> pointwise -> IFFT, one CTA per (b, h-pair). Two real rows are
// packed into one complex FFT (z = h0 + i*h1), unpacked/repacked in the
// frequency domain via Hermitian symmetry. Radix-4 Stockham, padded smem.
// ---------------------------------------------------------------------------
__device__ __forceinline__ float2 cmulf(float2 a, float2 b)
{
    return make_float2(fmaf(a.x, b.x, -a.y * b.y), fmaf(a.x, b.y, a.y * b.x));
}

template <bool INV, int NS>
__device__ __forceinline__ void fft_stage(const float2* __restrict__ src,
                                          float2* __restrict__ dst)
{
    constexpr int STEP = (NTOK / 4) / NS;   // 1024/NS
#pragma unroll
    for (int q = 0; q < 4; q++) {
        int j = threadIdx.x + q * 256;      // 0..1023
        int k = j & (NS - 1);
        float2 a0 = src[PAD(j)];
        float2 a1 = src[PAD(j + 1024)];
        float2 a2 = src[PAD(j + 2048)];
        float2 a3 = src[PAD(j + 3072)];
        int kk = k * STEP;
        float2 w1 = g_tw[kk];
        float2 w2 = g_tw[2 * kk];
        float2 w3 = g_tw[3 * kk];
        if (INV) { w1.y = -w1.y; w2.y = -w2.y; w3.y = -w3.y; }
        a1 = cmulf(w1, a1);
        a2 = cmulf(w2, a2);
        a3 = cmulf(w3, a3);
        float2 t0 = make_float2(a0.x + a2.x, a0.y + a2.y);
        float2 t1 = make_float2(a0.x - a2.x, a0.y - a2.y);
        float2 t2 = make_float2(a1.x + a3.x, a1.y + a3.y);
        float2 u  = make_float2(a1.x - a3.x, a1.y - a3.y);
        float2 t3 = INV ? make_float2(-u.y, u.x) : make_float2(u.y, -u.x);
        int base = ((j - k) << 2) + k;      // (j/NS)*4*NS + k
        dst[PAD(base         )] = make_float2(t0.x + t2.x, t0.y + t2.y);
        dst[PAD(base +     NS)] = make_float2(t1.x + t3.x, t1.y + t3.y);
        dst[PAD(base + 2 * NS)] = make_float2(t0.x - t2.x, t0.y - t2.y);
        dst[PAD(base + 3 * NS)] = make_float2(t1.x - t3.x, t1.y - t3.y);
    }
    __syncthreads();
}

template <bool INV>
__device__ __forceinline__ void fft6(float2* b0, float2* b1)
{
    fft_stage<INV, 1>(b0, b1);
    fft_stage<INV, 4>(b1, b0);
    fft_stage<INV, 16>(b0, b1);
    fft_stage<INV, 64>(b1, b0);
    fft_stage<INV, 256>(b0, b1);
    fft_stage<INV, 1024>(b1, b0);   // ends in b0
}

__device__ __forceinline__ float2 pointwise(float2 X, float ra, float ia,
                                            float rbv, float ibv)
{
    float xr = fmaxf(fmaf(ra, X.x, fmaf(-ia, X.y, rbv)), 0.0f);
    float xi = fmaxf(fmaf(ra, X.y, fmaf(ia, X.x, ibv)), 0.0f);
    return make_float2(xr, xi);
}

__global__ __launch_bounds__(256) void fftmix_k(
    const float* __restrict__ rmat, const float* __restrict__ imat,
    const float* __restrict__ rb,   const float* __restrict__ ib)
{
    extern __shared__ float2 sb[];
    float2* b0 = sb;
    float2* b1 = sb + FFT_BUF;

    int blk = blockIdx.x;               // b*384 + hp
    int b   = blk / (HID / 2);
    int hp  = blk % (HID / 2);
    int h0  = 2 * hp;
    int h1  = h0 + 1;
    float* row0 = g_ht + ((size_t)(b * HID + h0)) * NTOK;
    float* row1 = row0 + NTOK;
    int tid = threadIdx.x;

    // pack two real rows as one complex row
#pragma unroll
    for (int q = 0; q < 16; q++) {
        int t = tid + q * 256;
        b0[PAD(t)] = make_float2(row0[t], row1[t]);
    }
    __syncthreads();

    fft6<false>(b0, b1);                // Z in b0

    float ra0 = rmat[(size_t)h0 * HID + h0];
    float ia0 = imat[(size_t)h0 * HID + h0];
    float ra1 = rmat[(size_t)h1 * HID + h1];
    float ia1 = imat[(size_t)h1 * HID + h1];
    float rb0 = rb[h0], ib0 = ib[h0];
    float rb1 = rb[h1], ib1 = ib[h1];
    const float inv = 0.015625f;        // 1/sqrt(4096)

    // unpack -> pointwise -> Hermitian-project -> repack, pairwise (k, N-k)
    for (int p = tid; p < 2048; p += 256) {
        int k = p;
        int m = (NTOK - p) & (NTOK - 1);    // N-k mod N (p=0 -> 0)
#pragma unroll
        for (int rep = 0; rep < 2; rep++) {
            // rep 0: (k,m); for p==0 also handle Nyquist (2048,2048) on rep 1
            if (rep == 1) {
                if (p != 0) break;
                k = 2048; m = 2048;
            }
            float2 Zk = b0[PAD(k)];
            float2 Zm = b0[PAD(m)];
            // X0 = (Z[k]+conj(Z[m]))/2 * inv ; X1 = (Z[k]-conj(Z[m]))/(2i) * inv
            float hv = 0.5f * inv;
            float2 X0k = make_float2((Zk.x + Zm.x) * hv, (Zk.y - Zm.y) * hv);
            float2 X1k = make_float2((Zk.y + Zm.y) * hv, (Zm.x - Zk.x) * hv);
            float2 X0m = make_float2((Zm.x + Zk.x) * hv, (Zm.y - Zk.y) * hv);
            float2 X1m = make_float2((Zm.y + Zk.y) * hv, (Zk.x - Zm.x) * hv);

            float2 S0k = pointwise(X0k, ra0, ia0, rb0, ib0);
            float2 S0m = pointwise(X0m, ra0, ia0, rb0, ib0);
            float2 S1k = pointwise(X1k, ra1, ia1, rb1, ib1);
            float2 S1m = pointwise(X1m, ra1, ia1, rb1, ib1);

            // Hermitian parts: H[k] = (S[k]+conj(S[m]))/2, H[m]=conj(H[k])
            float2 H0 = make_float2(0.5f * (S0k.x + S0m.x), 0.5f * (S0k.y - S0m.y));
            float2 H1 = make_float2(0.5f * (S1k.x + S1m.x), 0.5f * (S1k.y - S1m.y));
            // T = H0 + i*H1 ; T[m] = conj(H0) + i*conj(H1)
            b0[PAD(k)] = make_float2(H0.x - H1.y, H0.y + H1.x);
            if (m != k)
                b0[PAD(m)] = make_float2(H0.x + H1.y, H1.x - H0.y);
        }
    }
    __syncthreads();

    fft6<true>(b0, b1);                 // y0 + i*y1 in b0

#pragma unroll
    for (int q = 0; q < 16; q++) {
        int t = tid + q * 256;
        float2 v = b0[PAD(t)];
        row0[t] = v.x * inv;
        row1[t] = v.y * inv;
    }
}

// ---------------------------------------------------------------------------
// GEMM2: y[b,n,c] = BN( sum_h ht[b,h,n] * W2[c,h] )
// 128(n) x 64(c) x 16(k) tile, 8x8 microtile, 128 threads.
// B-tile (ht) is k-major: direct vector copy, no transpose.
// ---------------------------------------------------------------------------
__global__ __launch_bounds__(128) void gemm2_k(
    const float* __restrict__ W2,
    const float* __restrict__ g2, const float* __restrict__ b2,
    const float* __restrict__ m2, const float* __restrict__ v2,
    float* __restrict__ y)
{
    __shared__ float sH[16][132];   // [k][n]
    __shared__ float sW[16][68];    // [k][c]

    int tid = threadIdx.x;
    int n0 = blockIdx.x * 128;
    int c0 = blockIdx.y * 64;
    int b  = blockIdx.z;

    const float* hp = g_ht + (size_t)b * HID * NTOK + n0;
    const float* wp = W2 + (size_t)c0 * HID;

    int hrow = tid >> 3;            // 0..15 (k row for sH copy)
    int fcol = (tid & 7) << 2;      // 0..28 (n float4 base)
    int crow = tid >> 1;            // 0..63 (c row for sW)
    int ck4  = (tid & 1) << 3;      // 0 or 8

    int tx = tid & 15;              // n group
    int ty = tid >> 4;              // c group (0..7)

    float acc[8][8];                // [n][c]
#pragma unroll
    for (int i = 0; i < 8; i++)
#pragma unroll
        for (int j = 0; j < 8; j++) acc[i][j] = 0.0f;

    for (int kc = 0; kc < HID; kc += 16) {
#pragma unroll
        for (int s = 0; s < 4; s++) {
            float4 v = *(const float4*)(hp + (size_t)(kc + hrow) * NTOK + fcol + s * 32);
            *(float4*)(&sH[hrow][fcol + s * 32]) = v;
        }
        {
            float4 v0 = *(const float4*)(wp + (size_t)crow * HID + kc + ck4);
            float4 v1 = *(const float4*)(wp + (size_t)crow * HID + kc + ck4 + 4);
            sW[ck4 + 0][crow] = v0.x; sW[ck4 + 1][crow] = v0.y;
            sW[ck4 + 2][crow] = v0.z; sW[ck4 + 3][crow] = v0.w;
            sW[ck4 + 4][crow] = v1.x; sW[ck4 + 5][crow] = v1.y;
            sW[ck4 + 6][crow] = v1.z; sW[ck4 + 7][crow] = v1.w;
        }
        __syncthreads();
#pragma unroll
        for (int k = 0; k < 16; k++) {
            float a[8], bb[8];
            *(float4*)(a)      = *(const float4*)(&sW[k][ty * 8]);
            *(float4*)(a + 4)  = *(const float4*)(&sW[k][ty * 8 + 4]);
            *(float4*)(bb)     = *(const float4*)(&sH[k][tx * 8]);
            *(float4*)(bb + 4) = *(const float4*)(&sH[k][tx * 8 + 4]);
#pragma unroll
            for (int i = 0; i < 8; i++)
#pragma unroll
                for (int j = 0; j < 8; j++)
                    acc[i][j] = fmaf(bb[i], a[j], acc[i][j]);
        }
        __syncthreads();
    }

    float sc[8], sh[8];
#pragma unroll
    for (int j = 0; j < 8; j++) {
        int c = c0 + ty * 8 + j;
        sc[j] = g2[c] * rsqrtf(v2[c] + EPSBN);
        sh[j] = b2[c] - m2[c] * sc[j];
    }
#pragma unroll
    for (int i = 0; i < 8; i++) {
        int n = n0 + tx * 8 + i;
        float* op = y + ((size_t)(b * NTOK + n) * CIN + c0 + ty * 8);
        float4 o0, o1;
        o0.x = fmaf(acc[i][0], sc[0], sh[0]);
        o0.y = fmaf(acc[i][1], sc[1], sh[1]);
        o0.z = fmaf(acc[i][2], sc[2], sh[2]);
        o0.w = fmaf(acc[i][3], sc[3], sh[3]);
        o1.x = fmaf(acc[i][4], sc[4], sh[4]);
        o1.y = fmaf(acc[i][5], sc[5], sh[5]);
        o1.z = fmaf(acc[i][6], sc[6], sh[6]);
        o1.w = fmaf(acc[i][7], sc[7], sh[7]);
        *(float4*)(op)     = o0;
        *(float4*)(op + 4) = o1;
    }
}

// ---------------------------------------------------------------------------
extern "C" void kernel_launch(void* const* d_in, const int* in_sizes, int n_in,
                              void* d_out, int out_size)
{
    const float* x  = (const float*)d_in[0];
    const float* W1 = (const float*)d_in[1];
    const float* g1 = (const float*)d_in[2];
    const float* b1 = (const float*)d_in[3];
    const float* m1 = (const float*)d_in[4];
    const float* v1 = (const float*)d_in[5];
    const float* r  = (const float*)d_in[6];
    const float* im = (const float*)d_in[7];
    const float* rb = (const float*)d_in[8];
    const float* ib = (const float*)d_in[9];
    const float* W2 = (const float*)d_in[10];
    const float* g2 = (const float*)d_in[11];
    const float* b2 = (const float*)d_in[12];
    const float* m2 = (const float*)d_in[13];
    const float* v2 = (const float*)d_in[14];
    float* y = (float*)d_out;

    static bool attr_set = false;
    if (!attr_set) {
        cudaFuncSetAttribute(fftmix_k, cudaFuncAttributeMaxDynamicSharedMemorySize,
                             2 * FFT_BUF * sizeof(float2));
        attr_set = true;
    }

    twiddle_init_k<<<16, 256>>>();
    gemm1_k<<<dim3(NTOK / 128, HID / 128, BATCH), 256>>>(x, W1, g1, b1, m1, v1);
    fftmix_k<<<BATCH * (HID / 2), 256, 2 * FFT_BUF * sizeof(float2)>>>(r, im, rb, ib);
    gemm2_k<<<dim3(NTOK / 128, CIN / 64, BATCH), 128>>>(W2, g2, b2, m2, v2, y);
}

// round 3
// speedup vs baseline: 1.5181x; 1.1617x over previous
#include <cuda_runtime.h>
#include <cstdint>

#define BATCH 8
#define NTOK  4096
#define CIN   192
#define HID   768
#define EPSBN 1e-5f

// Scratch: hidden activations, TRANSPOSED [B, H, N] so FFT rows are contiguous
// and GEMM2 reads K-major rows. ~100.7 MB.
__device__ float  g_ht[(size_t)BATCH * HID * NTOK];
__device__ float2 g_tw[NTOK];   // forward twiddles e^{-2*pi*i*t/N}

// padded smem index for FFT buffers: one extra float2 per 32
#define PAD(i) ((i) + ((i) >> 5))
#define FFT_BUF 4224            // PAD(4095)=4222 < 4224

// ---------------------------------------------------------------------------
__global__ void twiddle_init_k()
{
    int t = blockIdx.x * blockDim.x + threadIdx.x;
    if (t < NTOK) {
        float s, c;
        sincospif(-2.0f * (float)t / (float)NTOK, &s, &c);
        g_tw[t] = make_float2(c, s);
    }
}

// ---------------------------------------------------------------------------
// tf32 helpers
// ---------------------------------------------------------------------------
__device__ __forceinline__ uint32_t f2tf32(float x)
{
    uint32_t r;
    asm("cvt.rna.tf32.f32 %0, %1;" : "=r"(r) : "f"(x));
    return r;
}

__device__ __forceinline__ void mma_tf32(float4& d, const uint32_t* a, const uint32_t* b)
{
    asm volatile(
        "mma.sync.aligned.m16n8k8.row.col.f32.tf32.tf32.f32 "
        "{%0,%1,%2,%3}, {%4,%5,%6,%7}, {%8,%9}, {%0,%1,%2,%3};"
        : "+f"(d.x), "+f"(d.y), "+f"(d.z), "+f"(d.w)
        : "r"(a[0]), "r"(a[1]), "r"(a[2]), "r"(a[3]), "r"(b[0]), "r"(b[1]));
}

// ---------------------------------------------------------------------------
// GEMM1 (tf32 tensor): ht[b,h,n] = relu(BN( sum_c x[b,n,c] * W1[h,c] ))
// CTA tile 128(h) x 128(n) x 32(k); 8 warps: 2(m=h) x 4(n); warp tile 64x32.
// Each warp: 4 m-frags x 4 n-frags of m16n8k8.
// ---------------------------------------------------------------------------
__global__ __launch_bounds__(256) void gemm1_k(
    const float* __restrict__ x,  const float* __restrict__ W1,
    const float* __restrict__ g1, const float* __restrict__ b1,
    const float* __restrict__ m1, const float* __restrict__ v1)
{
    __shared__ uint32_t sW[32][132];   // [k][h]  (tf32 bits)
    __shared__ uint32_t sX[32][132];   // [k][n]

    int tid  = threadIdx.x;
    int lane = tid & 31;
    int wid  = tid >> 5;
    int wm   = wid & 1;        // h half (0..1)
    int wn   = wid >> 1;       // n quarter (0..3)
    int lk   = lane & 3;
    int lg   = lane >> 2;

    int n0 = blockIdx.x * 128;
    int h0 = blockIdx.y * 128;
    int b  = blockIdx.z;

    const float* xp = x  + ((size_t)b * NTOK + n0) * CIN;
    const float* wp = W1 + (size_t)h0 * CIN;

    // loader mapping: 2 threads per row, 16 consecutive floats each
    int lrow = tid >> 1;            // 0..127
    int lcb  = (tid & 1) << 4;      // 0 or 16

    float4 acc[4][4];
#pragma unroll
    for (int i = 0; i < 4; i++)
#pragma unroll
        for (int j = 0; j < 4; j++) acc[i][j] = make_float4(0.f, 0.f, 0.f, 0.f);

    for (int kc = 0; kc < CIN; kc += 32) {
#pragma unroll
        for (int s = 0; s < 4; s++) {
            float4 vx = *(const float4*)(xp + (size_t)lrow * CIN + kc + lcb + s * 4);
            float4 vw = *(const float4*)(wp + (size_t)lrow * CIN + kc + lcb + s * 4);
            int kk = lcb + s * 4;
            sX[kk + 0][lrow] = f2tf32(vx.x); sX[kk + 1][lrow] = f2tf32(vx.y);
            sX[kk + 2][lrow] = f2tf32(vx.z); sX[kk + 3][lrow] = f2tf32(vx.w);
            sW[kk + 0][lrow] = f2tf32(vw.x); sW[kk + 1][lrow] = f2tf32(vw.y);
            sW[kk + 2][lrow] = f2tf32(vw.z); sW[kk + 3][lrow] = f2tf32(vw.w);
        }
        __syncthreads();
#pragma unroll
        for (int k0 = 0; k0 < 32; k0 += 8) {
            uint32_t afr[4][4], bfr[4][2];
#pragma unroll
            for (int mf = 0; mf < 4; mf++) {
                int mb = wm * 64 + mf * 16 + lg;
                afr[mf][0] = sW[k0 + lk    ][mb];
                afr[mf][1] = sW[k0 + lk    ][mb + 8];
                afr[mf][2] = sW[k0 + lk + 4][mb];
                afr[mf][3] = sW[k0 + lk + 4][mb + 8];
            }
#pragma unroll
            for (int nf = 0; nf < 4; nf++) {
                int nb = wn * 32 + nf * 8 + lg;
                bfr[nf][0] = sX[k0 + lk    ][nb];
                bfr[nf][1] = sX[k0 + lk + 4][nb];
            }
#pragma unroll
            for (int mf = 0; mf < 4; mf++)
#pragma unroll
                for (int nf = 0; nf < 4; nf++)
                    mma_tf32(acc[mf][nf], afr[mf], bfr[nf]);
        }
        __syncthreads();
    }

    // epilogue: BN + ReLU, store to g_ht[h][n]
#pragma unroll
    for (int mf = 0; mf < 4; mf++) {
        int h_r0 = h0 + wm * 64 + mf * 16 + lg;
        int h_r1 = h_r0 + 8;
        float sc0 = g1[h_r0] * rsqrtf(v1[h_r0] + EPSBN);
        float sh0 = b1[h_r0] - m1[h_r0] * sc0;
        float sc1 = g1[h_r1] * rsqrtf(v1[h_r1] + EPSBN);
        float sh1 = b1[h_r1] - m1[h_r1] * sc1;
        float* p0 = g_ht + ((size_t)(b * HID + h_r0)) * NTOK + n0;
        float* p1 = g_ht + ((size_t)(b * HID + h_r1)) * NTOK + n0;
#pragma unroll
        for (int nf = 0; nf < 4; nf++) {
            int nc = wn * 32 + nf * 8 + 2 * lk;
            float4 a = acc[mf][nf];
            float2 o0, o1;
            o0.x = fmaxf(fmaf(a.x, sc0, sh0), 0.0f);
            o0.y = fmaxf(fmaf(a.y, sc0, sh0), 0.0f);
            o1.x = fmaxf(fmaf(a.z, sc1, sh1), 0.0f);
            o1.y = fmaxf(fmaf(a.w, sc1, sh1), 0.0f);
            *(float2*)(p0 + nc) = o0;
            *(float2*)(p1 + nc) = o1;
        }
    }
}

// ---------------------------------------------------------------------------
// Fused FFT -> pointwise -> IFFT, one CTA per (b, h-pair). Two real rows are
// packed into one complex FFT (z = h0 + i*h1), unpacked/repacked in the
// frequency domain via Hermitian symmetry. Radix-4 Stockham, padded smem.
// ---------------------------------------------------------------------------
__device__ __forceinline__ float2 cmulf(float2 a, float2 b)
{
    return make_float2(fmaf(a.x, b.x, -a.y * b.y), fmaf(a.x, b.y, a.y * b.x));
}

template <bool INV, int NS>
__device__ __forceinline__ void fft_stage(const float2* __restrict__ src,
                                          float2* __restrict__ dst)
{
    constexpr int STEP = (NTOK / 4) / NS;   // 1024/NS
#pragma unroll
    for (int q = 0; q < 4; q++) {
        int j = threadIdx.x + q * 256;      // 0..1023
        int k = j & (NS - 1);
        float2 a0 = src[PAD(j)];
        float2 a1 = src[PAD(j + 1024)];
        float2 a2 = src[PAD(j + 2048)];
        float2 a3 = src[PAD(j + 3072)];
        int kk = k * STEP;
        float2 w1 = g_tw[kk];
        float2 w2 = g_tw[2 * kk];
        float2 w3 = g_tw[3 * kk];
        if (INV) { w1.y = -w1.y; w2.y = -w2.y; w3.y = -w3.y; }
        a1 = cmulf(w1, a1);
        a2 = cmulf(w2, a2);
        a3 = cmulf(w3, a3);
        float2 t0 = make_float2(a0.x + a2.x, a0.y + a2.y);
        float2 t1 = make_float2(a0.x - a2.x, a0.y - a2.y);
        float2 t2 = make_float2(a1.x + a3.x, a1.y + a3.y);
        float2 u  = make_float2(a1.x - a3.x, a1.y - a3.y);
        float2 t3 = INV ? make_float2(-u.y, u.x) : make_float2(u.y, -u.x);
        int base = ((j - k) << 2) + k;      // (j/NS)*4*NS + k
        dst[PAD(base         )] = make_float2(t0.x + t2.x, t0.y + t2.y);
        dst[PAD(base +     NS)] = make_float2(t1.x + t3.x, t1.y + t3.y);
        dst[PAD(base + 2 * NS)] = make_float2(t0.x - t2.x, t0.y - t2.y);
        dst[PAD(base + 3 * NS)] = make_float2(t1.x - t3.x, t1.y - t3.y);
    }
    __syncthreads();
}

template <bool INV>
__device__ __forceinline__ void fft6(float2* b0, float2* b1)
{
    fft_stage<INV, 1>(b0, b1);
    fft_stage<INV, 4>(b1, b0);
    fft_stage<INV, 16>(b0, b1);
    fft_stage<INV, 64>(b1, b0);
    fft_stage<INV, 256>(b0, b1);
    fft_stage<INV, 1024>(b1, b0);   // ends in b0
}

__device__ __forceinline__ float2 pointwise(float2 X, float ra, float ia,
                                            float rbv, float ibv)
{
    float xr = fmaxf(fmaf(ra, X.x, fmaf(-ia, X.y, rbv)), 0.0f);
    float xi = fmaxf(fmaf(ra, X.y, fmaf(ia, X.x, ibv)), 0.0f);
    return make_float2(xr, xi);
}

__global__ __launch_bounds__(256) void fftmix_k(
    const float* __restrict__ rmat, const float* __restrict__ imat,
    const float* __restrict__ rb,   const float* __restrict__ ib)
{
    extern __shared__ float2 sb[];
    float2* b0 = sb;
    float2* b1 = sb + FFT_BUF;

    int blk = blockIdx.x;               // b*384 + hp
    int b   = blk / (HID / 2);
    int hp  = blk % (HID / 2);
    int h0  = 2 * hp;
    int h1  = h0 + 1;
    float* row0 = g_ht + ((size_t)(b * HID + h0)) * NTOK;
    float* row1 = row0 + NTOK;
    int tid = threadIdx.x;

    // pack two real rows as one complex row
#pragma unroll
    for (int q = 0; q < 16; q++) {
        int t = tid + q * 256;
        b0[PAD(t)] = make_float2(row0[t], row1[t]);
    }
    __syncthreads();

    fft6<false>(b0, b1);                // Z in b0

    float ra0 = rmat[(size_t)h0 * HID + h0];
    float ia0 = imat[(size_t)h0 * HID + h0];
    float ra1 = rmat[(size_t)h1 * HID + h1];
    float ia1 = imat[(size_t)h1 * HID + h1];
    float rb0 = rb[h0], ib0 = ib[h0];
    float rb1 = rb[h1], ib1 = ib[h1];
    const float inv = 0.015625f;        // 1/sqrt(4096)

    // unpack -> pointwise -> Hermitian-project -> repack, pairwise (k, N-k)
    for (int p = tid; p < 2048; p += 256) {
        int k = p;
        int m = (NTOK - p) & (NTOK - 1);    // N-k mod N (p=0 -> 0)
#pragma unroll
        for (int rep = 0; rep < 2; rep++) {
            // rep 0: (k,m); for p==0 also handle Nyquist (2048,2048) on rep 1
            if (rep == 1) {
                if (p != 0) break;
                k = 2048; m = 2048;
            }
            float2 Zk = b0[PAD(k)];
            float2 Zm = b0[PAD(m)];
            // X0 = (Z[k]+conj(Z[m]))/2 * inv ; X1 = (Z[k]-conj(Z[m]))/(2i) * inv
            float hv = 0.5f * inv;
            float2 X0k = make_float2((Zk.x + Zm.x) * hv, (Zk.y - Zm.y) * hv);
            float2 X1k = make_float2((Zk.y + Zm.y) * hv, (Zm.x - Zk.x) * hv);
            float2 X0m = make_float2((Zm.x + Zk.x) * hv, (Zm.y - Zk.y) * hv);
            float2 X1m = make_float2((Zm.y + Zk.y) * hv, (Zk.x - Zm.x) * hv);

            float2 S0k = pointwise(X0k, ra0, ia0, rb0, ib0);
            float2 S0m = pointwise(X0m, ra0, ia0, rb0, ib0);
            float2 S1k = pointwise(X1k, ra1, ia1, rb1, ib1);
            float2 S1m = pointwise(X1m, ra1, ia1, rb1, ib1);

            // Hermitian parts: H[k] = (S[k]+conj(S[m]))/2, H[m]=conj(H[k])
            float2 H0 = make_float2(0.5f * (S0k.x + S0m.x), 0.5f * (S0k.y - S0m.y));
            float2 H1 = make_float2(0.5f * (S1k.x + S1m.x), 0.5f * (S1k.y - S1m.y));
            // T = H0 + i*H1 ; T[m] = conj(H0) + i*conj(H1)
            b0[PAD(k)] = make_float2(H0.x - H1.y, H0.y + H1.x);
            if (m != k)
                b0[PAD(m)] = make_float2(H0.x + H1.y, H1.x - H0.y);
        }
    }
    __syncthreads();

    fft6<true>(b0, b1);                 // y0 + i*y1 in b0

#pragma unroll
    for (int q = 0; q < 16; q++) {
        int t = tid + q * 256;
        float2 v = b0[PAD(t)];
        row0[t] = v.x * inv;
        row1[t] = v.y * inv;
    }
}

// ---------------------------------------------------------------------------
// GEMM2 (tf32 tensor): y[b,n,c] = BN( sum_h ht[b,h,n] * W2[c,h] )
// CTA tile 256(n) x 64(c) x 32(k); 8 warps: 4(m=n) x 2(n=c); warp tile 64x32.
// ---------------------------------------------------------------------------
__global__ __launch_bounds__(256) void gemm2_k(
    const float* __restrict__ W2,
    const float* __restrict__ g2, const float* __restrict__ b2,
    const float* __restrict__ m2, const float* __restrict__ v2,
    float* __restrict__ y)
{
    __shared__ uint32_t sA[32][260];   // [k][n]  (tf32 bits of ht)
    __shared__ uint32_t sW[32][68];    // [k][c]

    int tid  = threadIdx.x;
    int lane = tid & 31;
    int wid  = tid >> 5;
    int wm   = wid >> 1;       // n quarter (0..3) -> 64 tokens each
    int wn   = wid & 1;        // c half (0..1)    -> 32 channels each
    int lk   = lane & 3;
    int lg   = lane >> 2;

    int n0 = blockIdx.x * 256;
    int c0 = blockIdx.y * 64;
    int b  = blockIdx.z;

    const float* hp = g_ht + (size_t)b * HID * NTOK + n0;
    const float* wp = W2 + (size_t)c0 * HID;

    // loaders
    int akrow = tid >> 3;           // 0..31 (k row of sA)
    int anb   = (tid & 7) << 5;     // 0,32,...,224
    int wcrow = tid >> 2;           // 0..63 (c row)
    int wkb   = (tid & 3) << 3;     // 0,8,16,24

    float4 acc[4][4];
#pragma unroll
    for (int i = 0; i < 4; i++)
#pragma unroll
        for (int j = 0; j < 4; j++) acc[i][j] = make_float4(0.f, 0.f, 0.f, 0.f);

    for (int kc = 0; kc < HID; kc += 32) {
#pragma unroll
        for (int s = 0; s < 8; s++) {
            float4 v = *(const float4*)(hp + (size_t)(kc + akrow) * NTOK + anb + s * 4);
            sA[akrow][anb + s * 4 + 0] = f2tf32(v.x);
            sA[akrow][anb + s * 4 + 1] = f2tf32(v.y);
            sA[akrow][anb + s * 4 + 2] = f2tf32(v.z);
            sA[akrow][anb + s * 4 + 3] = f2tf32(v.w);
        }
        {
            float4 v0 = *(const float4*)(wp + (size_t)wcrow * HID + kc + wkb);
            float4 v1 = *(const float4*)(wp + (size_t)wcrow * HID + kc + wkb + 4);
            sW[wkb + 0][wcrow] = f2tf32(v0.x); sW[wkb + 1][wcrow] = f2tf32(v0.y);
            sW[wkb + 2][wcrow] = f2tf32(v0.z); sW[wkb + 3][wcrow] = f2tf32(v0.w);
            sW[wkb + 4][wcrow] = f2tf32(v1.x); sW[wkb + 5][wcrow] = f2tf32(v1.y);
            sW[wkb + 6][wcrow] = f2tf32(v1.z); sW[wkb + 7][wcrow] = f2tf32(v1.w);
        }
        __syncthreads();
#pragma unroll
        for (int k0 = 0; k0 < 32; k0 += 8) {
            uint32_t afr[4][4], bfr[4][2];
#pragma unroll
            for (int mf = 0; mf < 4; mf++) {
                int mb = wm * 64 + mf * 16 + lg;
                afr[mf][0] = sA[k0 + lk    ][mb];
                afr[mf][1] = sA[k0 + lk    ][mb + 8];
                afr[mf][2] = sA[k0 + lk + 4][mb];
                afr[mf][3] = sA[k0 + lk + 4][mb + 8];
            }
#pragma unroll
            for (int nf = 0; nf < 4; nf++) {
                int nb = wn * 32 + nf * 8 + lg;
                bfr[nf][0] = sW[k0 + lk    ][nb];
                bfr[nf][1] = sW[k0 + lk + 4][nb];
            }
#pragma unroll
            for (int mf = 0; mf < 4; mf++)
#pragma unroll
                for (int nf = 0; nf < 4; nf++)
                    mma_tf32(acc[mf][nf], afr[mf], bfr[nf]);
        }
        __syncthreads();
    }

    // epilogue: BN, store y[b][n][c]
    float scv[4][2], shv[4][2];
#pragma unroll
    for (int nf = 0; nf < 4; nf++) {
        int c = c0 + wn * 32 + nf * 8 + 2 * lk;
#pragma unroll
        for (int j = 0; j < 2; j++) {
            scv[nf][j] = g2[c + j] * rsqrtf(v2[c + j] + EPSBN);
            shv[nf][j] = b2[c + j] - m2[c + j] * scv[nf][j];
        }
    }
#pragma unroll
    for (int mf = 0; mf < 4; mf++) {
        int n_r0 = n0 + wm * 64 + mf * 16 + lg;
        int n_r1 = n_r0 + 8;
        float* p0 = y + ((size_t)(b * NTOK + n_r0)) * CIN;
        float* p1 = y + ((size_t)(b * NTOK + n_r1)) * CIN;
#pragma unroll
        for (int nf = 0; nf < 4; nf++) {
            int c = c0 + wn * 32 + nf * 8 + 2 * lk;
            float4 a = acc[mf][nf];
            float2 o0, o1;
            o0.x = fmaf(a.x, scv[nf][0], shv[nf][0]);
            o0.y = fmaf(a.y, scv[nf][1], shv[nf][1]);
            o1.x = fmaf(a.z, scv[nf][0], shv[nf][0]);
            o1.y = fmaf(a.w, scv[nf][1], shv[nf][1]);
            *(float2*)(p0 + c) = o0;
            *(float2*)(p1 + c) = o1;
        }
    }
}

// ---------------------------------------------------------------------------
extern "C" void kernel_launch(void* const* d_in, const int* in_sizes, int n_in,
                              void* d_out, int out_size)
{
    const float* x  = (const float*)d_in[0];
    const float* W1 = (const float*)d_in[1];
    const float* g1 = (const float*)d_in[2];
    const float* b1 = (const float*)d_in[3];
    const float* m1 = (const float*)d_in[4];
    const float* v1 = (const float*)d_in[5];
    const float* r  = (const float*)d_in[6];
    const float* im = (const float*)d_in[7];
    const float* rb = (const float*)d_in[8];
    const float* ib = (const float*)d_in[9];
    const float* W2 = (const float*)d_in[10];
    const float* g2 = (const float*)d_in[11];
    const float* b2 = (const float*)d_in[12];
    const float* m2 = (const float*)d_in[13];
    const float* v2 = (const float*)d_in[14];
    float* y = (float*)d_out;

    static bool attr_set = false;
    if (!attr_set) {
        cudaFuncSetAttribute(fftmix_k, cudaFuncAttributeMaxDynamicSharedMemorySize,
                             2 * FFT_BUF * sizeof(float2));
        attr_set = true;
    }

    twiddle_init_k<<<16, 256>>>();
    gemm1_k<<<dim3(NTOK / 128, HID / 128, BATCH), 256>>>(x, W1, g1, b1, m1, v1);
    fftmix_k<<<BATCH * (HID / 2), 256, 2 * FFT_BUF * sizeof(float2)>>>(r, im, rb, ib);
    gemm2_k<<<dim3(NTOK / 256, CIN / 64, BATCH), 256>>>(W2, g2, b2, m2, v2, y);
}

// round 4
// speedup vs baseline: 2.4326x; 1.6024x over previous
#include <cuda_runtime.h>
#include <cstdint>

#define BATCH 8
#define NTOK  4096
#define CIN   192
#define HID   768
#define EPSBN 1e-5f

#define XT_N (BATCH * NTOK * CIN)   // 6291456
#define W_N  (HID * CIN)            // 147456

// Scratch
__device__ float  g_ht[(size_t)BATCH * HID * NTOK];   // hidden, [B,H,N], ~100.7MB
__device__ float  g_xt[XT_N];                         // tf32-rounded x
__device__ float  g_w1t[W_N];                         // tf32-rounded W1
__device__ float  g_w2t[W_N];                         // tf32-rounded W2
__device__ float2 g_tw[NTOK];                         // forward twiddles

// padded smem index for FFT buffers
#define PAD(i) ((i) + ((i) >> 5))
#define FFT_BUF 4224

// ---------------------------------------------------------------------------
__device__ __forceinline__ float tf32r(float x)
{
    uint32_t r;
    asm("cvt.rna.tf32.f32 %0, %1;" : "=r"(r) : "f"(x));
    return __uint_as_float(r);
}

__device__ __forceinline__ void mma_tf32(float4& d, const uint32_t* a, const uint32_t* b)
{
    asm volatile(
        "mma.sync.aligned.m16n8k8.row.col.f32.tf32.tf32.f32 "
        "{%0,%1,%2,%3}, {%4,%5,%6,%7}, {%8,%9}, {%0,%1,%2,%3};"
        : "+f"(d.x), "+f"(d.y), "+f"(d.z), "+f"(d.w)
        : "r"(a[0]), "r"(a[1]), "r"(a[2]), "r"(a[3]), "r"(b[0]), "r"(b[1]));
}

__device__ __forceinline__ void cp_async16(uint32_t saddr, const void* gptr)
{
    asm volatile("cp.async.cg.shared.global [%0], [%1], 16;" :: "r"(saddr), "l"(gptr));
}
#define CP_COMMIT() asm volatile("cp.async.commit_group;")
#define CP_WAIT1()  asm volatile("cp.async.wait_group 1;")

// ---------------------------------------------------------------------------
__global__ void twiddle_init_k()
{
    int t = blockIdx.x * blockDim.x + threadIdx.x;
    if (t < NTOK) {
        float s, c;
        sincospif(-2.0f * (float)t / (float)NTOK, &s, &c);
        g_tw[t] = make_float2(c, s);
    }
}

// RN-round inputs to tf32 once (so GEMMs can feed raw bits losslessly)
__global__ void prep_k(const float* __restrict__ x, const float* __restrict__ W1,
                       const float* __restrict__ W2)
{
    int idx = blockIdx.x * blockDim.x + threadIdx.x;   // float4 index
    const float4* src;
    float4* dst;
    int off;
    if (idx < XT_N / 4)                 { src = (const float4*)x;  dst = (float4*)g_xt;  off = idx; }
    else if (idx < (XT_N + W_N) / 4)    { src = (const float4*)W1; dst = (float4*)g_w1t; off = idx - XT_N / 4; }
    else                                { src = (const float4*)W2; dst = (float4*)g_w2t; off = idx - (XT_N + W_N) / 4; }
    float4 v = src[off];
    v.x = tf32r(v.x); v.y = tf32r(v.y); v.z = tf32r(v.z); v.w = tf32r(v.w);
    dst[off] = v;
}

// ---------------------------------------------------------------------------
// GEMM1 (tf32, cp.async 3-stage): ht[b,h,n] = relu(BN( sum_c x[b,n,c]*W1[h,c] ))
// CTA 128(h) x 128(n) x k16; warps 2(h) x 4(n); warp 64x32; NC=12 chunks.
// smem: A=W1 tile [h128][k16] stride 20 ; B=x tile [n128][k16] stride 20.
// ---------------------------------------------------------------------------
#define G1_SSZ (128 * 20 * 2)
#define G1_SMEM (3 * G1_SSZ * 4)

__global__ __launch_bounds__(256) void gemm1_k(
    const float* __restrict__ g1, const float* __restrict__ b1,
    const float* __restrict__ m1, const float* __restrict__ v1)
{
    extern __shared__ uint32_t smem_u[];

    int tid  = threadIdx.x;
    int lane = tid & 31;
    int wid  = tid >> 5;
    int wm   = wid & 1;
    int wn   = wid >> 1;
    int lk   = lane & 3;
    int lg   = lane >> 2;

    int n0 = blockIdx.x * 128;
    int h0 = blockIdx.y * 128;
    int b  = blockIdx.z;

    const float* wp = g_w1t + (size_t)h0 * CIN;
    const float* xp = g_xt + ((size_t)b * NTOK + n0) * CIN;

    uint32_t sbase = (uint32_t)__cvta_generic_to_shared(smem_u);

    int lrow = tid >> 2;            // 0..63 base row for loader
    int lko  = (tid & 3) << 2;      // 0,4,8,12

#define G1_LOAD(st, kc)                                                          \
    {                                                                            \
        uint32_t ao = sbase + (st) * G1_SSZ * 4;                                 \
        uint32_t bo = ao + 128 * 20 * 4;                                         \
        _Pragma("unroll")                                                        \
        for (int i = 0; i < 2; i++) {                                            \
            int row = lrow + i * 64;                                             \
            cp_async16(ao + (row * 20 + lko) * 4, wp + (size_t)row * CIN + (kc) * 16 + lko); \
            cp_async16(bo + (row * 20 + lko) * 4, xp + (size_t)row * CIN + (kc) * 16 + lko); \
        }                                                                        \
    }

    float4 acc[4][4];
#pragma unroll
    for (int i = 0; i < 4; i++)
#pragma unroll
        for (int j = 0; j < 4; j++) acc[i][j] = make_float4(0.f, 0.f, 0.f, 0.f);

    G1_LOAD(0, 0); CP_COMMIT();
    G1_LOAD(1, 1); CP_COMMIT();

    for (int kc = 0; kc < 12; kc++) {
        CP_WAIT1();
        __syncthreads();
        if (kc + 2 < 12) { G1_LOAD((kc + 2) % 3, kc + 2); }
        CP_COMMIT();

        const uint32_t* sA = smem_u + (kc % 3) * G1_SSZ;   // [h][k] stride 20
        const uint32_t* sB = sA + 128 * 20;                // [n][k] stride 20
#pragma unroll
        for (int k0 = 0; k0 < 16; k0 += 8) {
            uint32_t afr[4][4], bfr[4][2];
#pragma unroll
            for (int mf = 0; mf < 4; mf++) {
                int mb = wm * 64 + mf * 16 + lg;
                afr[mf][0] = sA[(mb    ) * 20 + k0 + lk    ];
                afr[mf][1] = sA[(mb + 8) * 20 + k0 + lk    ];
                afr[mf][2] = sA[(mb    ) * 20 + k0 + lk + 4];
                afr[mf][3] = sA[(mb + 8) * 20 + k0 + lk + 4];
            }
#pragma unroll
            for (int nf = 0; nf < 4; nf++) {
                int nb = wn * 32 + nf * 8 + lg;
                bfr[nf][0] = sB[nb * 20 + k0 + lk    ];
                bfr[nf][1] = sB[nb * 20 + k0 + lk + 4];
            }
#pragma unroll
            for (int mf = 0; mf < 4; mf++)
#pragma unroll
                for (int nf = 0; nf < 4; nf++)
                    mma_tf32(acc[mf][nf], afr[mf], bfr[nf]);
        }
    }

    // epilogue: BN + ReLU, store to g_ht[h][n]
#pragma unroll
    for (int mf = 0; mf < 4; mf++) {
        int h_r0 = h0 + wm * 64 + mf * 16 + lg;
        int h_r1 = h_r0 + 8;
        float sc0 = g1[h_r0] * rsqrtf(v1[h_r0] + EPSBN);
        float sh0 = b1[h_r0] - m1[h_r0] * sc0;
        float sc1 = g1[h_r1] * rsqrtf(v1[h_r1] + EPSBN);
        float sh1 = b1[h_r1] - m1[h_r1] * sc1;
        float* p0 = g_ht + ((size_t)(b * HID + h_r0)) * NTOK + n0;
        float* p1 = g_ht + ((size_t)(b * HID + h_r1)) * NTOK + n0;
#pragma unroll
        for (int nf = 0; nf < 4; nf++) {
            int nc = wn * 32 + nf * 8 + 2 * lk;
            float4 a = acc[mf][nf];
            float2 o0, o1;
            o0.x = fmaxf(fmaf(a.x, sc0, sh0), 0.0f);
            o0.y = fmaxf(fmaf(a.y, sc0, sh0), 0.0f);
            o1.x = fmaxf(fmaf(a.z, sc1, sh1), 0.0f);
            o1.y = fmaxf(fmaf(a.w, sc1, sh1), 0.0f);
            *(float2*)(p0 + nc) = o0;
            *(float2*)(p1 + nc) = o1;
        }
    }
}

// ---------------------------------------------------------------------------
// Fused FFT -> pointwise -> IFFT (unchanged except tf32-rounded output store)
// ---------------------------------------------------------------------------
__device__ __forceinline__ float2 cmulf(float2 a, float2 b)
{
    return make_float2(fmaf(a.x, b.x, -a.y * b.y), fmaf(a.x, b.y, a.y * b.x));
}

template <bool INV, int NS>
__device__ __forceinline__ void fft_stage(const float2* __restrict__ src,
                                          float2* __restrict__ dst)
{
    constexpr int STEP = (NTOK / 4) / NS;
#pragma unroll
    for (int q = 0; q < 4; q++) {
        int j = threadIdx.x + q * 256;
        int k = j & (NS - 1);
        float2 a0 = src[PAD(j)];
        float2 a1 = src[PAD(j + 1024)];
        float2 a2 = src[PAD(j + 2048)];
        float2 a3 = src[PAD(j + 3072)];
        int kk = k * STEP;
        float2 w1 = g_tw[kk];
        float2 w2 = g_tw[2 * kk];
        float2 w3 = g_tw[3 * kk];
        if (INV) { w1.y = -w1.y; w2.y = -w2.y; w3.y = -w3.y; }
        a1 = cmulf(w1, a1);
        a2 = cmulf(w2, a2);
        a3 = cmulf(w3, a3);
        float2 t0 = make_float2(a0.x + a2.x, a0.y + a2.y);
        float2 t1 = make_float2(a0.x - a2.x, a0.y - a2.y);
        float2 t2 = make_float2(a1.x + a3.x, a1.y + a3.y);
        float2 u  = make_float2(a1.x - a3.x, a1.y - a3.y);
        float2 t3 = INV ? make_float2(-u.y, u.x) : make_float2(u.y, -u.x);
        int base = ((j - k) << 2) + k;
        dst[PAD(base         )] = make_float2(t0.x + t2.x, t0.y + t2.y);
        dst[PAD(base +     NS)] = make_float2(t1.x + t3.x, t1.y + t3.y);
        dst[PAD(base + 2 * NS)] = make_float2(t0.x - t2.x, t0.y - t2.y);
        dst[PAD(base + 3 * NS)] = make_float2(t1.x - t3.x, t1.y - t3.y);
    }
    __syncthreads();
}

template <bool INV>
__device__ __forceinline__ void fft6(float2* b0, float2* b1)
{
    fft_stage<INV, 1>(b0, b1);
    fft_stage<INV, 4>(b1, b0);
    fft_stage<INV, 16>(b0, b1);
    fft_stage<INV, 64>(b1, b0);
    fft_stage<INV, 256>(b0, b1);
    fft_stage<INV, 1024>(b1, b0);
}

__device__ __forceinline__ float2 pointwise(float2 X, float ra, float ia,
                                            float rbv, float ibv)
{
    float xr = fmaxf(fmaf(ra, X.x, fmaf(-ia, X.y, rbv)), 0.0f);
    float xi = fmaxf(fmaf(ra, X.y, fmaf(ia, X.x, ibv)), 0.0f);
    return make_float2(xr, xi);
}

__global__ __launch_bounds__(256) void fftmix_k(
    const float* __restrict__ rmat, const float* __restrict__ imat,
    const float* __restrict__ rb,   const float* __restrict__ ib)
{
    extern __shared__ float2 sb[];
    float2* b0 = sb;
    float2* b1 = sb + FFT_BUF;

    int blk = blockIdx.x;
    int b   = blk / (HID / 2);
    int hp  = blk % (HID / 2);
    int h0  = 2 * hp;
    int h1  = h0 + 1;
    float* row0 = g_ht + ((size_t)(b * HID + h0)) * NTOK;
    float* row1 = row0 + NTOK;
    int tid = threadIdx.x;

#pragma unroll
    for (int q = 0; q < 16; q++) {
        int t = tid + q * 256;
        b0[PAD(t)] = make_float2(row0[t], row1[t]);
    }
    __syncthreads();

    fft6<false>(b0, b1);

    float ra0 = rmat[(size_t)h0 * HID + h0];
    float ia0 = imat[(size_t)h0 * HID + h0];
    float ra1 = rmat[(size_t)h1 * HID + h1];
    float ia1 = imat[(size_t)h1 * HID + h1];
    float rb0 = rb[h0], ib0 = ib[h0];
    float rb1 = rb[h1], ib1 = ib[h1];
    const float inv = 0.015625f;

    for (int p = tid; p < 2048; p += 256) {
        int k = p;
        int m = (NTOK - p) & (NTOK - 1);
#pragma unroll
        for (int rep = 0; rep < 2; rep++) {
            if (rep == 1) {
                if (p != 0) break;
                k = 2048; m = 2048;
            }
            float2 Zk = b0[PAD(k)];
            float2 Zm = b0[PAD(m)];
            float hv = 0.5f * inv;
            float2 X0k = make_float2((Zk.x + Zm.x) * hv, (Zk.y - Zm.y) * hv);
            float2 X1k = make_float2((Zk.y + Zm.y) * hv, (Zm.x - Zk.x) * hv);
            float2 X0m = make_float2((Zm.x + Zk.x) * hv, (Zm.y - Zk.y) * hv);
            float2 X1m = make_float2((Zm.y + Zk.y) * hv, (Zk.x - Zm.x) * hv);

            float2 S0k = pointwise(X0k, ra0, ia0, rb0, ib0);
            float2 S0m = pointwise(X0m, ra0, ia0, rb0, ib0);
            float2 S1k = pointwise(X1k, ra1, ia1, rb1, ib1);
            float2 S1m = pointwise(X1m, ra1, ia1, rb1, ib1);

            float2 H0 = make_float2(0.5f * (S0k.x + S0m.x), 0.5f * (S0k.y - S0m.y));
            float2 H1 = make_float2(0.5f * (S1k.x + S1m.x), 0.5f * (S1k.y - S1m.y));
            b0[PAD(k)] = make_float2(H0.x - H1.y, H0.y + H1.x);
            if (m != k)
                b0[PAD(m)] = make_float2(H0.x + H1.y, H1.x - H0.y);
        }
    }
    __syncthreads();

    fft6<true>(b0, b1);

#pragma unroll
    for (int q = 0; q < 16; q++) {
        int t = tid + q * 256;
        float2 v = b0[PAD(t)];
        row0[t] = tf32r(v.x * inv);    // pre-round for GEMM2's tf32 A operand
        row1[t] = tf32r(v.y * inv);
    }
}

// ---------------------------------------------------------------------------
// GEMM2 (tf32, cp.async 3-stage): y[b,n,c] = BN( sum_h ht[b,h,n] * W2[c,h] )
// CTA 256(n) x 64(c) x k16; warps 4(n) x 2(c); warp 64x32; NC=48 chunks.
// smem: A=ht tile [k16][n256] stride 264 ; B=W2 tile [c64][k16] stride 20.
// ---------------------------------------------------------------------------
#define G2_ASZ (16 * 264)
#define G2_WSZ (64 * 20)
#define G2_SSZ (G2_ASZ + G2_WSZ)
#define G2_SMEM (3 * G2_SSZ * 4)

__global__ __launch_bounds__(256) void gemm2_k(
    const float* __restrict__ g2, const float* __restrict__ b2,
    const float* __restrict__ m2, const float* __restrict__ v2,
    float* __restrict__ y)
{
    extern __shared__ uint32_t smem_u[];

    int tid  = threadIdx.x;
    int lane = tid & 31;
    int wid  = tid >> 5;
    int wm   = wid >> 1;       // n quarter
    int wn   = wid & 1;        // c half
    int lk   = lane & 3;
    int lg   = lane >> 2;

    int n0 = blockIdx.x * 256;
    int c0 = blockIdx.y * 64;
    int b  = blockIdx.z;

    const float* hp = g_ht + (size_t)b * HID * NTOK + n0;
    const float* wp = g_w2t + (size_t)c0 * HID;

    uint32_t sbase = (uint32_t)__cvta_generic_to_shared(smem_u);

    int arow = tid >> 6;            // 0..3 base k-row
    int aoff = (tid & 63) << 2;     // 0..252
    int wrow = tid >> 2;            // 0..63 c-row
    int woff = (tid & 3) << 2;      // 0,4,8,12

#define G2_LOAD(st, kc)                                                          \
    {                                                                            \
        uint32_t ao = sbase + (st) * G2_SSZ * 4;                                 \
        uint32_t wo = ao + G2_ASZ * 4;                                           \
        _Pragma("unroll")                                                        \
        for (int i = 0; i < 4; i++) {                                            \
            int row = arow + i * 4;                                              \
            cp_async16(ao + (row * 264 + aoff) * 4,                              \
                       hp + (size_t)((kc) * 16 + row) * NTOK + aoff);            \
        }                                                                        \
        cp_async16(wo + (wrow * 20 + woff) * 4,                                  \
                   wp + (size_t)wrow * HID + (kc) * 16 + woff);                  \
    }

    float4 acc[4][4];
#pragma unroll
    for (int i = 0; i < 4; i++)
#pragma unroll
        for (int j = 0; j < 4; j++) acc[i][j] = make_float4(0.f, 0.f, 0.f, 0.f);

    G2_LOAD(0, 0); CP_COMMIT();
    G2_LOAD(1, 1); CP_COMMIT();

    for (int kc = 0; kc < 48; kc++) {
        CP_WAIT1();
        __syncthreads();
        if (kc + 2 < 48) { G2_LOAD((kc + 2) % 3, kc + 2); }
        CP_COMMIT();

        const uint32_t* sA = smem_u + (kc % 3) * G2_SSZ;   // [k][n] stride 264
        const uint32_t* sW = sA + G2_ASZ;                  // [c][k] stride 20
#pragma unroll
        for (int k0 = 0; k0 < 16; k0 += 8) {
            uint32_t afr[4][4], bfr[4][2];
#pragma unroll
            for (int mf = 0; mf < 4; mf++) {
                int mb = wm * 64 + mf * 16 + lg;
                afr[mf][0] = sA[(k0 + lk    ) * 264 + mb    ];
                afr[mf][1] = sA[(k0 + lk    ) * 264 + mb + 8];
                afr[mf][2] = sA[(k0 + lk + 4) * 264 + mb    ];
                afr[mf][3] = sA[(k0 + lk + 4) * 264 + mb + 8];
            }
#pragma unroll
            for (int nf = 0; nf < 4; nf++) {
                int cb = wn * 32 + nf * 8 + lg;
                bfr[nf][0] = sW[cb * 20 + k0 + lk    ];
                bfr[nf][1] = sW[cb * 20 + k0 + lk + 4];
            }
#pragma unroll
            for (int mf = 0; mf < 4; mf++)
#pragma unroll
                for (int nf = 0; nf < 4; nf++)
                    mma_tf32(acc[mf][nf], afr[mf], bfr[nf]);
        }
    }

    // epilogue: BN, store y[b][n][c]
    float scv[4][2], shv[4][2];
#pragma unroll
    for (int nf = 0; nf < 4; nf++) {
        int c = c0 + wn * 32 + nf * 8 + 2 * lk;
#pragma unroll
        for (int j = 0; j < 2; j++) {
            scv[nf][j] = g2[c + j] * rsqrtf(v2[c + j] + EPSBN);
            shv[nf][j] = b2[c + j] - m2[c + j] * scv[nf][j];
        }
    }
#pragma unroll
    for (int mf = 0; mf < 4; mf++) {
        int n_r0 = n0 + wm * 64 + mf * 16 + lg;
        int n_r1 = n_r0 + 8;
        float* p0 = y + ((size_t)(b * NTOK + n_r0)) * CIN;
        float* p1 = y + ((size_t)(b * NTOK + n_r1)) * CIN;
#pragma unroll
        for (int nf = 0; nf < 4; nf++) {
            int c = c0 + wn * 32 + nf * 8 + 2 * lk;
            float4 a = acc[mf][nf];
            float2 o0, o1;
            o0.x = fmaf(a.x, scv[nf][0], shv[nf][0]);
            o0.y = fmaf(a.y, scv[nf][1], shv[nf][1]);
            o1.x = fmaf(a.z, scv[nf][0], shv[nf][0]);
            o1.y = fmaf(a.w, scv[nf][1], shv[nf][1]);
            *(float2*)(p0 + c) = o0;
            *(float2*)(p1 + c) = o1;
        }
    }
}

// ---------------------------------------------------------------------------
extern "C" void kernel_launch(void* const* d_in, const int* in_sizes, int n_in,
                              void* d_out, int out_size)
{
    const float* x  = (const float*)d_in[0];
    const float* W1 = (const float*)d_in[1];
    const float* g1 = (const float*)d_in[2];
    const float* b1 = (const float*)d_in[3];
    const float* m1 = (const float*)d_in[4];
    const float* v1 = (const float*)d_in[5];
    const float* r  = (const float*)d_in[6];
    const float* im = (const float*)d_in[7];
    const float* rb = (const float*)d_in[8];
    const float* ib = (const float*)d_in[9];
    const float* W2 = (const float*)d_in[10];
    const float* g2 = (const float*)d_in[11];
    const float* b2 = (const float*)d_in[12];
    const float* m2 = (const float*)d_in[13];
    const float* v2 = (const float*)d_in[14];
    float* y = (float*)d_out;

    static bool attr_set = false;
    if (!attr_set) {
        cudaFuncSetAttribute(fftmix_k, cudaFuncAttributeMaxDynamicSharedMemorySize,
                             2 * FFT_BUF * sizeof(float2));
        cudaFuncSetAttribute(gemm1_k, cudaFuncAttributeMaxDynamicSharedMemorySize, G1_SMEM);
        cudaFuncSetAttribute(gemm2_k, cudaFuncAttributeMaxDynamicSharedMemorySize, G2_SMEM);
        attr_set = true;
    }

    prep_k<<<(XT_N + 2 * W_N) / 4 / 256, 256>>>(x, W1, W2);
    twiddle_init_k<<<16, 256>>>();
    gemm1_k<<<dim3(NTOK / 128, HID / 128, BATCH), 256, G1_SMEM>>>(g1, b1, m1, v1);
    fftmix_k<<<BATCH * (HID / 2), 256, 2 * FFT_BUF * sizeof(float2)>>>(r, im, rb, ib);
    gemm2_k<<<dim3(NTOK / 256, CIN / 64, BATCH), 256, G2_SMEM>>>(g2, b2, m2, v2, y);
}